// round 13
// baseline (speedup 1.0000x reference)
#include <cuda_runtime.h>
#include <cuda_bf16.h>
#include <cstdint>

// ---------------------------------------------------------------------------
// Int8Linear on GB300 (sm_103a). Exact int8 math on bf16 tensor pipe.
// R13 (from R12 @338us, gemm 288us, ~1300cyc/iter serial overhead):
//   WARP SPECIALIZATION: warp0 = MMA issuer, warps1-3 = cp.async producers.
//   full[s] (96 arrivals) / done[s] (tcgen05.commit) mbarrier pairs,
//   no __syncthreads in the mainloop. Tile unchanged: BM=256 BN=256, 3 stages.
// ---------------------------------------------------------------------------

#if defined(__CUDA_ARCH__) && (defined(__CUDA_ARCH_FEAT_SM103_ALL) || defined(__CUDA_ARCH_FEAT_SM100_ALL) || defined(__CUDA_ARCH_FEAT_SM101_ALL))
#define HAS_TC 1
#else
#define HAS_TC 0
#endif

#define K_DIM 4096
#define N_DIM 4096
#define MAX_T 8192

#define BM 256                // CTA M tile (2 x 128 subtiles)
#define SM_TILE 128           // MMA M per dispatch
#define BN 256
#define BK_EL 64              // bf16 K elements per stage (128B rows)
#define STAGES 3
#define KSTEPS 4              // BK_EL / 16
#define NIT (K_DIM / BK_EL)   // 64

#define A_SUB_BYTES (SM_TILE * 128)                    // 16384 per subtile
#define B_STAGE_BYTES (BN * 128)                       // 32768
#define STAGE_BYTES (2 * A_SUB_BYTES + B_STAGE_BYTES)  // 65536

#define OFF_TMEM   0u
#define OFF_FULL   16u        // full[0..2] @ +16,+24,+32
#define OFF_DONE   40u        // done[0..2] @ +40,+48,+56
#define OFF_WS     1024u      // 256 floats
#define OFF_BIAS   2048u      // 256 floats
#define OFF_STAGE  4096u
#define SMEM_TOTAL (OFF_STAGE + STAGES * STAGE_BYTES)  // 200704

#define NPROD 96              // producer threads (warps 1-3)

// scratch (allocation-free rule: device globals)
__device__ __nv_bfloat16 g_qx[(size_t)MAX_T * K_DIM];
__device__ float         g_xscale[MAX_T];
__device__ __nv_bfloat16 g_wb[(size_t)N_DIM * K_DIM];
__device__ int           g_w_is_int32;

// ---------------------------------------------------------------------------
__device__ __forceinline__ uint32_t smem_u32(const void* p) {
    return (uint32_t)__cvta_generic_to_shared(p);
}
__device__ __forceinline__ void cp_async16(uint32_t s, const void* g) {
    asm volatile("cp.async.cg.shared.global [%0], [%1], 16;\n" :: "r"(s), "l"(g));
}
__device__ __forceinline__ void cp_commit() {
    asm volatile("cp.async.commit_group;\n" ::: "memory");
}
__device__ __forceinline__ uint32_t pack_bf16x2(float a, float b) {
    __nv_bfloat162 h = __floats2bfloat162_rn(a, b);
    return *reinterpret_cast<uint32_t*>(&h);
}
__device__ __forceinline__ uint32_t elect_one() {
    uint32_t pred;
    asm volatile(
        "{\n\t.reg .pred p;\n\t"
        "elect.sync _|p, 0xFFFFFFFF;\n\t"
        "selp.b32 %0, 1, 0, p;\n\t}"
        : "=r"(pred));
    return pred;
}

// ---------------------------------------------------------------------------
__global__ void detect_kernel(const int* __restrict__ w) {
    if (threadIdx.x == 0 && blockIdx.x == 0) {
        int ok = 1;
#pragma unroll
        for (int i = 0; i < 64; ++i) {
            int v = w[i];
            if (v < -200 || v > 200) ok = 0;
        }
        g_w_is_int32 = ok;
    }
}

__global__ void pack_kernel(const void* __restrict__ w) {
    const size_t idx = (size_t)blockIdx.x * blockDim.x + threadIdx.x;
    float f0, f1, f2, f3;
    if (g_w_is_int32) {
        const int4 v = reinterpret_cast<const int4*>(w)[idx];
        f0 = (float)v.x; f1 = (float)v.y; f2 = (float)v.z; f3 = (float)v.w;
    } else {
        const uint32_t p = reinterpret_cast<const uint32_t*>(w)[idx];
        f0 = (float)(int)(int8_t)(p & 0xff);
        f1 = (float)(int)(int8_t)((p >> 8) & 0xff);
        f2 = (float)(int)(int8_t)((p >> 16) & 0xff);
        f3 = (float)(int)(int8_t)(p >> 24);
    }
    uint2 o;
    o.x = pack_bf16x2(f0, f1);
    o.y = pack_bf16x2(f2, f3);
    reinterpret_cast<uint2*>(g_wb)[idx] = o;
}

// ---------------------------------------------------------------------------
__global__ void quant_kernel(const float* __restrict__ x) {
    const int row = blockIdx.x;
    const int t   = threadIdx.x;
    const float* xr = x + (size_t)row * K_DIM;

    float4 v[4];
    float amax = 0.f;
#pragma unroll
    for (int i = 0; i < 4; ++i) {
        v[i] = reinterpret_cast<const float4*>(xr)[t + i * 256];
        amax = fmaxf(amax, fmaxf(fmaxf(fabsf(v[i].x), fabsf(v[i].y)),
                                 fmaxf(fabsf(v[i].z), fabsf(v[i].w))));
    }

    __shared__ float smax[8];
#pragma unroll
    for (int o = 16; o > 0; o >>= 1)
        amax = fmaxf(amax, __shfl_xor_sync(0xffffffffu, amax, o));
    if ((t & 31) == 0) smax[t >> 5] = amax;
    __syncthreads();
    if (t < 32) {
        float m = (t < 8) ? smax[t] : 0.f;
#pragma unroll
        for (int o = 4; o > 0; o >>= 1)
            m = fmaxf(m, __shfl_xor_sync(0xffffffffu, m, o));
        if (t == 0) smax[0] = m;
    }
    __syncthreads();

    const float scale = smax[0] / 127.0f;
    if (t == 0) g_xscale[row] = scale;
    const float sdiv = (scale > 0.f) ? scale : 1.f;

    uint2* qrow = reinterpret_cast<uint2*>(g_qx + (size_t)row * K_DIM);
#pragma unroll
    for (int i = 0; i < 4; ++i) {
        float f[4] = {v[i].x, v[i].y, v[i].z, v[i].w};
#pragma unroll
        for (int j = 0; j < 4; ++j) {
            float q = rintf(f[j] / sdiv);
            f[j] = fminf(fmaxf(q, -127.f), 127.f);
        }
        uint2 o;
        o.x = pack_bf16x2(f[0], f[1]);
        o.y = pack_bf16x2(f[2], f[3]);
        qrow[t + i * 256] = o;
    }
}

// ===========================================================================
// tcgen05 kind::f16 GEMM (sm_103a cubin)
// ===========================================================================
#if HAS_TC
__device__ __forceinline__ void mbar_init(uint32_t a, uint32_t cnt) {
    asm volatile("mbarrier.init.shared.b64 [%0], %1;" :: "r"(a), "r"(cnt) : "memory");
}
__device__ __forceinline__ void mbar_arrive(uint32_t a) {
    asm volatile("mbarrier.arrive.shared.b64 _, [%0];" :: "r"(a) : "memory");
}
__device__ __forceinline__ void mbar_wait(uint32_t a, uint32_t parity) {
    asm volatile(
        "{\n\t.reg .pred P;\n\t"
        "W_%=:\n\t"
        "mbarrier.try_wait.parity.acquire.cta.shared::cta.b64 P, [%0], %1, 0x989680;\n\t"
        "@!P bra W_%=;\n\t}"
        :: "r"(a), "r"(parity) : "memory");
}
__device__ __forceinline__ void tc_commit(uint32_t bar) {
    asm volatile(
        "tcgen05.commit.cta_group::1.mbarrier::arrive::one.shared::cluster.b64 [%0];"
        :: "r"(bar) : "memory");
}
#define SW128(off) ((off) ^ (((off) >> 3) & 0x70))
__device__ __forceinline__ uint64_t make_desc_sw128(uint32_t base) {
    const uint64_t DESC_BASE =
        (uint64_t(2)  << 61) | (uint64_t(1) << 46) |
        (uint64_t(64) << 32) | (uint64_t(1) << 16);
    return DESC_BASE | ((uint64_t)(base >> 4) & 0x3FFF);
}
// kind::f16 idesc: F32@4, BF16@7, BF16@10, N-field [16:23)=N/4, M-field=(M>>4)<<24
#define MMA_IDESC ((1u << 4) | (1u << 7) | (1u << 10) | ((BN / 4) << 16) | ((SM_TILE >> 4) << 24))

__device__ __forceinline__ void mma_f16_ss(uint32_t d_tmem, uint64_t a_desc,
                                           uint64_t b_desc, uint32_t en) {
    asm volatile(
        "{\n\t.reg .pred p;\n\t"
        "setp.ne.u32 p, %5, 0;\n\t"
        "tcgen05.mma.cta_group::1.kind::f16 [%0], %1, %2, %3, {%4, %4, %4, %4}, p;\n\t}"
        :: "r"(d_tmem), "l"(a_desc), "l"(b_desc), "r"(MMA_IDESC), "r"(0u), "r"(en)
        : "memory");
}
#endif  // HAS_TC

#if HAS_TC
__global__ void __launch_bounds__(128) __cluster_dims__(1, 1, 1)
#else
__global__ void __launch_bounds__(128)
#endif
gemm_tc(const float* __restrict__ wscale,
        const float* __restrict__ bias,
        float* __restrict__ out) {
#if HAS_TC
    extern __shared__ char smem[];
    const uint32_t sb = smem_u32(smem);
    const int bn = blockIdx.x, bm = blockIdx.y;
    const int tid = threadIdx.x, wid = tid >> 5, lane = tid & 31;

    // Warp 0 allocs 512 TMEM cols (D0 @ 0, D1 @ 256); no relinquish (R9 fix).
    if (wid == 0) {
        asm volatile("tcgen05.alloc.cta_group::1.sync.aligned.shared::cta.b32 [%0], %1;"
                     :: "r"(sb + OFF_TMEM), "r"(512u) : "memory");
    }

    if (tid == 0) {
#pragma unroll
        for (int s = 0; s < STAGES; ++s) {
            mbar_init(sb + OFF_FULL + 8 * s, NPROD);  // 96 producer arrivals
            mbar_init(sb + OFF_DONE + 8 * s, 1);      // one tcgen05.commit
        }
    }
#pragma unroll
    for (int i = tid; i < BN; i += 128) {
        const int n0 = bn * BN;
        ((float*)(smem + OFF_WS))[i]   = wscale[n0 + i];
        ((float*)(smem + OFF_BIAS))[i] = bias[n0 + i];
    }
    __syncthreads();

    uint32_t tmem;
    asm volatile("ld.shared.b32 %0, [%1];" : "=r"(tmem) : "r"(sb + OFF_TMEM));

    const __nv_bfloat16* Ag = g_qx + (size_t)(bm * BM) * K_DIM;       // 256 rows
    const __nv_bfloat16* Bg = g_wb + (size_t)(bn * BN) * K_DIM;

    if (wid == 0) {
        // ================= CONSUMER: MMA issuer =================
        for (int it = 0; it < NIT; ++it) {
            const int b = it % STAGES;
            mbar_wait(sb + OFF_FULL + 8 * b, (it / STAGES) & 1);
            asm volatile("fence.proxy.async.shared::cta;" ::: "memory");
            asm volatile("tcgen05.fence::after_thread_sync;" ::: "memory");
            if (elect_one()) {
                const uint32_t base = sb + OFF_STAGE + b * STAGE_BYTES;
                const uint64_t a0d = make_desc_sw128(base);
                const uint64_t a1d = make_desc_sw128(base + A_SUB_BYTES);
                const uint64_t bd  = make_desc_sw128(base + 2 * A_SUB_BYTES);
                const uint32_t en0 = (it > 0) ? 1u : 0u;
#pragma unroll
                for (int k = 0; k < KSTEPS; ++k) {    // K=16 step -> +2 desc units
                    const uint32_t en = (k > 0) ? 1u : en0;
                    mma_f16_ss(tmem,       a0d + k * 2, bd + k * 2, en);
                    mma_f16_ss(tmem + 256, a1d + k * 2, bd + k * 2, en);
                }
                tc_commit(sb + OFF_DONE + 8 * b);
            }
        }
        // final MMA completion before epilogue
        mbar_wait(sb + OFF_DONE + 8 * ((NIT - 1) % STAGES),
                  ((NIT - 1) / STAGES) & 1);
    } else {
        // ================= PRODUCER: cp.async loaders =================
        const int ltid = tid - 32;   // 0..95

        // stage loader: [A0 16K][A1 16K][B 32K], SW128, 16B cp.async
#define LOAD_STAGE_P(IT)                                                        \
    do {                                                                        \
        const uint32_t _base = sb + OFF_STAGE + ((IT) % STAGES) * STAGE_BYTES;  \
        const int _k0 = (IT) * BK_EL;                                           \
        for (int _c = ltid; _c < 2048; _c += NPROD) {  /* A: 256 rows */        \
            int _r = _c >> 3, _ce = (_c & 7) << 3;                              \
            uint32_t _sub = (_r >= SM_TILE) ? 1u : 0u;                          \
            uint32_t _lr = _r & (SM_TILE - 1);                                  \
            uint32_t _off = (uint32_t)(_lr * 128 + _ce * 2);                    \
            cp_async16(_base + _sub * A_SUB_BYTES + SW128(_off),                \
                       Ag + (size_t)_r * K_DIM + _k0 + _ce);                    \
        }                                                                       \
        for (int _c = ltid; _c < 2048; _c += NPROD) {  /* B: 256 rows */        \
            int _r = _c >> 3, _ce = (_c & 7) << 3;                              \
            uint32_t _off = (uint32_t)(_r * 128 + _ce * 2);                     \
            cp_async16(_base + 2 * A_SUB_BYTES + SW128(_off),                   \
                       Bg + (size_t)_r * K_DIM + _k0 + _ce);                    \
        }                                                                       \
        cp_commit();                                                            \
    } while (0)

        for (int it = 0; it < NIT; ++it) {
            const int b = it % STAGES;
            // buffer b reuse: MMA of iteration it-STAGES must be done
            if (it >= STAGES)
                mbar_wait(sb + OFF_DONE + 8 * b, (it / STAGES - 1) & 1);
            LOAD_STAGE_P(it);
            // lag-2 arrival: group for stage it-2 has completed
            if (it >= 2) {
                asm volatile("cp.async.wait_group 2;" ::: "memory");
                mbar_arrive(sb + OFF_FULL + 8 * ((it - 2) % STAGES));
            }
        }
        // drain
        asm volatile("cp.async.wait_group 1;" ::: "memory");
        mbar_arrive(sb + OFF_FULL + 8 * ((NIT - 2) % STAGES));
        asm volatile("cp.async.wait_group 0;" ::: "memory");
        mbar_arrive(sb + OFF_FULL + 8 * ((NIT - 1) % STAGES));
    }

    __syncthreads();   // consumer has verified final MMA completion

    // ---- epilogue: fp32 TMEM (2 subtiles) -> dequant -> gmem ----
    asm volatile("tcgen05.fence::after_thread_sync;" ::: "memory");

    const float* wsS = (const float*)(smem + OFF_WS);
    const float* bS  = (const float*)(smem + OFF_BIAS);

#pragma unroll
    for (int sub = 0; sub < 2; ++sub) {
        const int m = bm * BM + sub * SM_TILE + wid * 32 + lane;
        const float xs = g_xscale[m];
        float* orow = out + (size_t)m * N_DIM + bn * BN;
        const uint32_t dbase = tmem + sub * 256;

#pragma unroll
        for (int ch = 0; ch < BN / 32; ++ch) {
            uint32_t r[32];
            asm volatile(
                "tcgen05.ld.sync.aligned.32x32b.x32.b32 "
                "{%0, %1, %2, %3, %4, %5, %6, %7, "
                " %8, %9, %10, %11, %12, %13, %14, %15, "
                " %16, %17, %18, %19, %20, %21, %22, %23, "
                " %24, %25, %26, %27, %28, %29, %30, %31}, [%32];"
                : "=r"(r[0]),  "=r"(r[1]),  "=r"(r[2]),  "=r"(r[3]),
                  "=r"(r[4]),  "=r"(r[5]),  "=r"(r[6]),  "=r"(r[7]),
                  "=r"(r[8]),  "=r"(r[9]),  "=r"(r[10]), "=r"(r[11]),
                  "=r"(r[12]), "=r"(r[13]), "=r"(r[14]), "=r"(r[15]),
                  "=r"(r[16]), "=r"(r[17]), "=r"(r[18]), "=r"(r[19]),
                  "=r"(r[20]), "=r"(r[21]), "=r"(r[22]), "=r"(r[23]),
                  "=r"(r[24]), "=r"(r[25]), "=r"(r[26]), "=r"(r[27]),
                  "=r"(r[28]), "=r"(r[29]), "=r"(r[30]), "=r"(r[31])
                : "r"(dbase + ch * 32));
            asm volatile("tcgen05.wait::ld.sync.aligned;" ::: "memory");

#pragma unroll
            for (int q = 0; q < 8; ++q) {
                const int c = ch * 32 + q * 4;
                float4 v;
                v.x = __uint_as_float(r[q * 4 + 0]) * wsS[c + 0] * xs + bS[c + 0];
                v.y = __uint_as_float(r[q * 4 + 1]) * wsS[c + 1] * xs + bS[c + 1];
                v.z = __uint_as_float(r[q * 4 + 2]) * wsS[c + 2] * xs + bS[c + 2];
                v.w = __uint_as_float(r[q * 4 + 3]) * wsS[c + 3] * xs + bS[c + 3];
                *reinterpret_cast<float4*>(orow + c) = v;
            }
        }
    }

    __syncthreads();
    if (tid == 0) {
#pragma unroll
        for (int s = 0; s < STAGES; ++s) {
            asm volatile("mbarrier.inval.shared.b64 [%0];"
                         :: "r"(sb + OFF_FULL + 8 * s) : "memory");
            asm volatile("mbarrier.inval.shared.b64 [%0];"
                         :: "r"(sb + OFF_DONE + 8 * s) : "memory");
        }
    }
    __syncthreads();
    if (wid == 0) {
        asm volatile("tcgen05.dealloc.cta_group::1.sync.aligned.b32 %0, %1;"
                     :: "r"(tmem), "r"(512u));
    }
#endif  // HAS_TC
}

// ---------------------------------------------------------------------------
extern "C" void kernel_launch(void* const* d_in, const int* in_sizes, int n_in,
                              void* d_out, int out_size) {
    const float* x      = (const float*)d_in[0];
    const void*  weight = d_in[1];
    const float* wscale = (const float*)d_in[2];
    const float* bias   = (const float*)d_in[3];
    float* out = (float*)d_out;

    const int T = in_sizes[0] / K_DIM;   // 8192

    cudaFuncSetAttribute(gemm_tc, cudaFuncAttributeMaxDynamicSharedMemorySize,
                         SMEM_TOTAL);

    detect_kernel<<<1, 32>>>((const int*)weight);
    pack_kernel<<<(N_DIM * K_DIM / 4) / 256, 256>>>(weight);
    quant_kernel<<<T, 256>>>(x);

    dim3 grid_tc(N_DIM / BN, T / BM);   // (16, 32) = 512 CTAs
    gemm_tc<<<grid_tc, 128, SMEM_TOTAL>>>(wscale, bias, out);
}

// round 14
// speedup vs baseline: 1.3473x; 1.3473x over previous
#include <cuda_runtime.h>
#include <cuda_bf16.h>
#include <cstdint>

// ---------------------------------------------------------------------------
// Int8Linear on GB300 (sm_103a). Exact int8 math on bf16 tensor pipe.
// R14 (from R12 @338us best; R13 warp-spec regressed due to slow producers):
//   blockDim 160: warps 0-3 = producers (R12's exact unrolled loader),
//   warp 4 = MMA issuer. full[s] (128 arrivals) / done[s] (tcgen05.commit).
//   No __syncthreads in mainloop. Tile BM=256 BN=256, 3 stages.
// ---------------------------------------------------------------------------

#if defined(__CUDA_ARCH__) && (defined(__CUDA_ARCH_FEAT_SM103_ALL) || defined(__CUDA_ARCH_FEAT_SM100_ALL) || defined(__CUDA_ARCH_FEAT_SM101_ALL))
#define HAS_TC 1
#else
#define HAS_TC 0
#endif

#define K_DIM 4096
#define N_DIM 4096
#define MAX_T 8192

#define BM 256                // CTA M tile (2 x 128 subtiles)
#define SM_TILE 128           // MMA M per dispatch
#define BN 256
#define BK_EL 64              // bf16 K elements per stage (128B rows)
#define STAGES 3
#define KSTEPS 4              // BK_EL / 16
#define NIT (K_DIM / BK_EL)   // 64

#define A_SUB_BYTES (SM_TILE * 128)                    // 16384 per subtile
#define B_STAGE_BYTES (BN * 128)                       // 32768
#define STAGE_BYTES (2 * A_SUB_BYTES + B_STAGE_BYTES)  // 65536

#define OFF_TMEM   0u
#define OFF_FULL   16u        // full[0..2] @ +16,+24,+32
#define OFF_DONE   40u        // done[0..2] @ +40,+48,+56
#define OFF_WS     1024u      // 256 floats
#define OFF_BIAS   2048u      // 256 floats
#define OFF_STAGE  4096u
#define SMEM_TOTAL (OFF_STAGE + STAGES * STAGE_BYTES)  // 200704

#define NPROD 128             // producer threads (warps 0-3)
#define MMA_WID 4             // MMA issuer warp

// scratch (allocation-free rule: device globals)
__device__ __nv_bfloat16 g_qx[(size_t)MAX_T * K_DIM];
__device__ float         g_xscale[MAX_T];
__device__ __nv_bfloat16 g_wb[(size_t)N_DIM * K_DIM];
__device__ int           g_w_is_int32;

// ---------------------------------------------------------------------------
__device__ __forceinline__ uint32_t smem_u32(const void* p) {
    return (uint32_t)__cvta_generic_to_shared(p);
}
__device__ __forceinline__ void cp_async16(uint32_t s, const void* g) {
    asm volatile("cp.async.cg.shared.global [%0], [%1], 16;\n" :: "r"(s), "l"(g));
}
__device__ __forceinline__ void cp_commit() {
    asm volatile("cp.async.commit_group;\n" ::: "memory");
}
__device__ __forceinline__ uint32_t pack_bf16x2(float a, float b) {
    __nv_bfloat162 h = __floats2bfloat162_rn(a, b);
    return *reinterpret_cast<uint32_t*>(&h);
}
__device__ __forceinline__ uint32_t elect_one() {
    uint32_t pred;
    asm volatile(
        "{\n\t.reg .pred p;\n\t"
        "elect.sync _|p, 0xFFFFFFFF;\n\t"
        "selp.b32 %0, 1, 0, p;\n\t}"
        : "=r"(pred));
    return pred;
}

// ---------------------------------------------------------------------------
__global__ void detect_kernel(const int* __restrict__ w) {
    if (threadIdx.x == 0 && blockIdx.x == 0) {
        int ok = 1;
#pragma unroll
        for (int i = 0; i < 64; ++i) {
            int v = w[i];
            if (v < -200 || v > 200) ok = 0;
        }
        g_w_is_int32 = ok;
    }
}

__global__ void pack_kernel(const void* __restrict__ w) {
    const size_t idx = (size_t)blockIdx.x * blockDim.x + threadIdx.x;
    float f0, f1, f2, f3;
    if (g_w_is_int32) {
        const int4 v = reinterpret_cast<const int4*>(w)[idx];
        f0 = (float)v.x; f1 = (float)v.y; f2 = (float)v.z; f3 = (float)v.w;
    } else {
        const uint32_t p = reinterpret_cast<const uint32_t*>(w)[idx];
        f0 = (float)(int)(int8_t)(p & 0xff);
        f1 = (float)(int)(int8_t)((p >> 8) & 0xff);
        f2 = (float)(int)(int8_t)((p >> 16) & 0xff);
        f3 = (float)(int)(int8_t)(p >> 24);
    }
    uint2 o;
    o.x = pack_bf16x2(f0, f1);
    o.y = pack_bf16x2(f2, f3);
    reinterpret_cast<uint2*>(g_wb)[idx] = o;
}

// ---------------------------------------------------------------------------
__global__ void quant_kernel(const float* __restrict__ x) {
    const int row = blockIdx.x;
    const int t   = threadIdx.x;
    const float* xr = x + (size_t)row * K_DIM;

    float4 v[4];
    float amax = 0.f;
#pragma unroll
    for (int i = 0; i < 4; ++i) {
        v[i] = reinterpret_cast<const float4*>(xr)[t + i * 256];
        amax = fmaxf(amax, fmaxf(fmaxf(fabsf(v[i].x), fabsf(v[i].y)),
                                 fmaxf(fabsf(v[i].z), fabsf(v[i].w))));
    }

    __shared__ float smax[8];
#pragma unroll
    for (int o = 16; o > 0; o >>= 1)
        amax = fmaxf(amax, __shfl_xor_sync(0xffffffffu, amax, o));
    if ((t & 31) == 0) smax[t >> 5] = amax;
    __syncthreads();
    if (t < 32) {
        float m = (t < 8) ? smax[t] : 0.f;
#pragma unroll
        for (int o = 4; o > 0; o >>= 1)
            m = fmaxf(m, __shfl_xor_sync(0xffffffffu, m, o));
        if (t == 0) smax[0] = m;
    }
    __syncthreads();

    const float scale = smax[0] / 127.0f;
    if (t == 0) g_xscale[row] = scale;
    const float sdiv = (scale > 0.f) ? scale : 1.f;

    uint2* qrow = reinterpret_cast<uint2*>(g_qx + (size_t)row * K_DIM);
#pragma unroll
    for (int i = 0; i < 4; ++i) {
        float f[4] = {v[i].x, v[i].y, v[i].z, v[i].w};
#pragma unroll
        for (int j = 0; j < 4; ++j) {
            float q = rintf(f[j] / sdiv);
            f[j] = fminf(fmaxf(q, -127.f), 127.f);
        }
        uint2 o;
        o.x = pack_bf16x2(f[0], f[1]);
        o.y = pack_bf16x2(f[2], f[3]);
        qrow[t + i * 256] = o;
    }
}

// ===========================================================================
// tcgen05 kind::f16 GEMM (sm_103a cubin)
// ===========================================================================
#if HAS_TC
__device__ __forceinline__ void mbar_init(uint32_t a, uint32_t cnt) {
    asm volatile("mbarrier.init.shared.b64 [%0], %1;" :: "r"(a), "r"(cnt) : "memory");
}
__device__ __forceinline__ void mbar_arrive(uint32_t a) {
    asm volatile("mbarrier.arrive.shared.b64 _, [%0];" :: "r"(a) : "memory");
}
__device__ __forceinline__ void mbar_wait(uint32_t a, uint32_t parity) {
    asm volatile(
        "{\n\t.reg .pred P;\n\t"
        "W_%=:\n\t"
        "mbarrier.try_wait.parity.acquire.cta.shared::cta.b64 P, [%0], %1, 0x989680;\n\t"
        "@!P bra W_%=;\n\t}"
        :: "r"(a), "r"(parity) : "memory");
}
__device__ __forceinline__ void tc_commit(uint32_t bar) {
    asm volatile(
        "tcgen05.commit.cta_group::1.mbarrier::arrive::one.shared::cluster.b64 [%0];"
        :: "r"(bar) : "memory");
}
#define SW128(off) ((off) ^ (((off) >> 3) & 0x70))
__device__ __forceinline__ uint64_t make_desc_sw128(uint32_t base) {
    const uint64_t DESC_BASE =
        (uint64_t(2)  << 61) | (uint64_t(1) << 46) |
        (uint64_t(64) << 32) | (uint64_t(1) << 16);
    return DESC_BASE | ((uint64_t)(base >> 4) & 0x3FFF);
}
// kind::f16 idesc: F32@4, BF16@7, BF16@10, N-field [16:23)=N/4, M-field=(M>>4)<<24
#define MMA_IDESC ((1u << 4) | (1u << 7) | (1u << 10) | ((BN / 4) << 16) | ((SM_TILE >> 4) << 24))

__device__ __forceinline__ void mma_f16_ss(uint32_t d_tmem, uint64_t a_desc,
                                           uint64_t b_desc, uint32_t en) {
    asm volatile(
        "{\n\t.reg .pred p;\n\t"
        "setp.ne.u32 p, %5, 0;\n\t"
        "tcgen05.mma.cta_group::1.kind::f16 [%0], %1, %2, %3, {%4, %4, %4, %4}, p;\n\t}"
        :: "r"(d_tmem), "l"(a_desc), "l"(b_desc), "r"(MMA_IDESC), "r"(0u), "r"(en)
        : "memory");
}
#endif  // HAS_TC

#if HAS_TC
__global__ void __launch_bounds__(160) __cluster_dims__(1, 1, 1)
#else
__global__ void __launch_bounds__(160)
#endif
gemm_tc(const float* __restrict__ wscale,
        const float* __restrict__ bias,
        float* __restrict__ out) {
#if HAS_TC
    extern __shared__ char smem[];
    const uint32_t sb = smem_u32(smem);
    const int bn = blockIdx.x, bm = blockIdx.y;
    const int tid = threadIdx.x, wid = tid >> 5, lane = tid & 31;

    // MMA warp allocs 512 TMEM cols (test_mma_mxf8_512 pattern: alloc from
    // the MMA warp). No relinquish (R9 fix).
    if (wid == MMA_WID) {
        asm volatile("tcgen05.alloc.cta_group::1.sync.aligned.shared::cta.b32 [%0], %1;"
                     :: "r"(sb + OFF_TMEM), "r"(512u) : "memory");
    }

    if (tid == 0) {
#pragma unroll
        for (int s = 0; s < STAGES; ++s) {
            mbar_init(sb + OFF_FULL + 8 * s, NPROD);  // 128 producer arrivals
            mbar_init(sb + OFF_DONE + 8 * s, 1);      // one tcgen05.commit
        }
    }
    if (tid < BN) {   // 160 threads; first 128 + next 32 handle 256 entries
        const int n0 = bn * BN;
        ((float*)(smem + OFF_WS))[tid]   = wscale[n0 + tid];
        ((float*)(smem + OFF_BIAS))[tid] = bias[n0 + tid];
    }
    if (tid + 160 < BN) {
        const int n0 = bn * BN;
        ((float*)(smem + OFF_WS))[tid + 160]   = wscale[n0 + tid + 160];
        ((float*)(smem + OFF_BIAS))[tid + 160] = bias[n0 + tid + 160];
    }
    __syncthreads();

    uint32_t tmem;
    asm volatile("ld.shared.b32 %0, [%1];" : "=r"(tmem) : "r"(sb + OFF_TMEM));

    const __nv_bfloat16* Ag = g_qx + (size_t)(bm * BM) * K_DIM;       // 256 rows
    const __nv_bfloat16* Bg = g_wb + (size_t)(bn * BN) * K_DIM;

    if (wid == MMA_WID) {
        // ================= CONSUMER: MMA issuer (warp 4) =================
        for (int it = 0; it < NIT; ++it) {
            const int b = it % STAGES;
            mbar_wait(sb + OFF_FULL + 8 * b, (it / STAGES) & 1);
            asm volatile("fence.proxy.async.shared::cta;" ::: "memory");
            asm volatile("tcgen05.fence::after_thread_sync;" ::: "memory");
            if (elect_one()) {
                const uint32_t base = sb + OFF_STAGE + b * STAGE_BYTES;
                const uint64_t a0d = make_desc_sw128(base);
                const uint64_t a1d = make_desc_sw128(base + A_SUB_BYTES);
                const uint64_t bd  = make_desc_sw128(base + 2 * A_SUB_BYTES);
                const uint32_t en0 = (it > 0) ? 1u : 0u;
#pragma unroll
                for (int k = 0; k < KSTEPS; ++k) {    // K=16 step -> +2 desc units
                    const uint32_t en = (k > 0) ? 1u : en0;
                    mma_f16_ss(tmem,       a0d + k * 2, bd + k * 2, en);
                    mma_f16_ss(tmem + 256, a1d + k * 2, bd + k * 2, en);
                }
                tc_commit(sb + OFF_DONE + 8 * b);
            }
        }
        // final MMA completion before epilogue
        mbar_wait(sb + OFF_DONE + 8 * ((NIT - 1) % STAGES),
                  ((NIT - 1) / STAGES) & 1);
    } else {
        // ============ PRODUCER: warps 0-3, R12's exact unrolled loader ======
#define LOAD_STAGE_P(IT)                                                        \
    do {                                                                        \
        const uint32_t _base = sb + OFF_STAGE + ((IT) % STAGES) * STAGE_BYTES;  \
        const int _k0 = (IT) * BK_EL;                                           \
        _Pragma("unroll")                                                       \
        for (int _i = 0; _i < 16; ++_i) {  /* A: 256 rows in 2 subtiles */      \
            int _c = tid + _i * NPROD;                                          \
            int _r = _c >> 3, _ce = (_c & 7) << 3;                              \
            uint32_t _sub = (_r >= SM_TILE) ? 1u : 0u;                          \
            uint32_t _lr = _r & (SM_TILE - 1);                                  \
            uint32_t _off = (uint32_t)(_lr * 128 + _ce * 2);                    \
            cp_async16(_base + _sub * A_SUB_BYTES + SW128(_off),                \
                       Ag + (size_t)_r * K_DIM + _k0 + _ce);                    \
        }                                                                       \
        _Pragma("unroll")                                                       \
        for (int _i = 0; _i < 16; ++_i) {  /* B: 256 rows */                    \
            int _c = tid + _i * NPROD;                                          \
            int _r = _c >> 3, _ce = (_c & 7) << 3;                              \
            uint32_t _off = (uint32_t)(_r * 128 + _ce * 2);                     \
            cp_async16(_base + 2 * A_SUB_BYTES + SW128(_off),                   \
                       Bg + (size_t)_r * K_DIM + _k0 + _ce);                    \
        }                                                                       \
        cp_commit();                                                            \
    } while (0)

        for (int it = 0; it < NIT; ++it) {
            const int b = it % STAGES;
            // buffer b reuse: MMA of iteration it-STAGES must be done
            if (it >= STAGES)
                mbar_wait(sb + OFF_DONE + 8 * b, (it / STAGES - 1) & 1);
            LOAD_STAGE_P(it);
            // lag-2 arrival: group for stage it-2 has completed
            if (it >= 2) {
                asm volatile("cp.async.wait_group 2;" ::: "memory");
                mbar_arrive(sb + OFF_FULL + 8 * ((it - 2) % STAGES));
            }
        }
        // drain
        asm volatile("cp.async.wait_group 1;" ::: "memory");
        mbar_arrive(sb + OFF_FULL + 8 * ((NIT - 2) % STAGES));
        asm volatile("cp.async.wait_group 0;" ::: "memory");
        mbar_arrive(sb + OFF_FULL + 8 * ((NIT - 1) % STAGES));
    }

    __syncthreads();   // consumer verified final MMA completion

    // ---- epilogue: warps 0-3 read TMEM, dequant, store ----
    asm volatile("tcgen05.fence::after_thread_sync;" ::: "memory");

    const float* wsS = (const float*)(smem + OFF_WS);
    const float* bS  = (const float*)(smem + OFF_BIAS);

    if (wid < 4) {
#pragma unroll
        for (int sub = 0; sub < 2; ++sub) {
            const int m = bm * BM + sub * SM_TILE + wid * 32 + lane;
            const float xs = g_xscale[m];
            float* orow = out + (size_t)m * N_DIM + bn * BN;
            const uint32_t dbase = tmem + sub * 256;

#pragma unroll
            for (int ch = 0; ch < BN / 32; ++ch) {
                uint32_t r[32];
                asm volatile(
                    "tcgen05.ld.sync.aligned.32x32b.x32.b32 "
                    "{%0, %1, %2, %3, %4, %5, %6, %7, "
                    " %8, %9, %10, %11, %12, %13, %14, %15, "
                    " %16, %17, %18, %19, %20, %21, %22, %23, "
                    " %24, %25, %26, %27, %28, %29, %30, %31}, [%32];"
                    : "=r"(r[0]),  "=r"(r[1]),  "=r"(r[2]),  "=r"(r[3]),
                      "=r"(r[4]),  "=r"(r[5]),  "=r"(r[6]),  "=r"(r[7]),
                      "=r"(r[8]),  "=r"(r[9]),  "=r"(r[10]), "=r"(r[11]),
                      "=r"(r[12]), "=r"(r[13]), "=r"(r[14]), "=r"(r[15]),
                      "=r"(r[16]), "=r"(r[17]), "=r"(r[18]), "=r"(r[19]),
                      "=r"(r[20]), "=r"(r[21]), "=r"(r[22]), "=r"(r[23]),
                      "=r"(r[24]), "=r"(r[25]), "=r"(r[26]), "=r"(r[27]),
                      "=r"(r[28]), "=r"(r[29]), "=r"(r[30]), "=r"(r[31])
                    : "r"(dbase + ch * 32));
                asm volatile("tcgen05.wait::ld.sync.aligned;" ::: "memory");

#pragma unroll
                for (int q = 0; q < 8; ++q) {
                    const int c = ch * 32 + q * 4;
                    float4 v;
                    v.x = __uint_as_float(r[q * 4 + 0]) * wsS[c + 0] * xs + bS[c + 0];
                    v.y = __uint_as_float(r[q * 4 + 1]) * wsS[c + 1] * xs + bS[c + 1];
                    v.z = __uint_as_float(r[q * 4 + 2]) * wsS[c + 2] * xs + bS[c + 2];
                    v.w = __uint_as_float(r[q * 4 + 3]) * wsS[c + 3] * xs + bS[c + 3];
                    *reinterpret_cast<float4*>(orow + c) = v;
                }
            }
        }
    }

    __syncthreads();
    if (tid == 0) {
#pragma unroll
        for (int s = 0; s < STAGES; ++s) {
            asm volatile("mbarrier.inval.shared.b64 [%0];"
                         :: "r"(sb + OFF_FULL + 8 * s) : "memory");
            asm volatile("mbarrier.inval.shared.b64 [%0];"
                         :: "r"(sb + OFF_DONE + 8 * s) : "memory");
        }
    }
    __syncthreads();
    if (wid == MMA_WID) {
        asm volatile("tcgen05.dealloc.cta_group::1.sync.aligned.b32 %0, %1;"
                     :: "r"(tmem), "r"(512u));
    }
#endif  // HAS_TC
}

// ---------------------------------------------------------------------------
extern "C" void kernel_launch(void* const* d_in, const int* in_sizes, int n_in,
                              void* d_out, int out_size) {
    const float* x      = (const float*)d_in[0];
    const void*  weight = d_in[1];
    const float* wscale = (const float*)d_in[2];
    const float* bias   = (const float*)d_in[3];
    float* out = (float*)d_out;

    const int T = in_sizes[0] / K_DIM;   // 8192

    cudaFuncSetAttribute(gemm_tc, cudaFuncAttributeMaxDynamicSharedMemorySize,
                         SMEM_TOTAL);

    detect_kernel<<<1, 32>>>((const int*)weight);
    pack_kernel<<<(N_DIM * K_DIM / 4) / 256, 256>>>(weight);
    quant_kernel<<<T, 256>>>(x);

    dim3 grid_tc(N_DIM / BN, T / BM);   // (16, 32) = 512 CTAs
    gemm_tc<<<grid_tc, 160, SMEM_TOTAL>>>(wscale, bias, out);
}

// round 15
// speedup vs baseline: 1.5487x; 1.1495x over previous
#include <cuda_runtime.h>
#include <cuda_bf16.h>
#include <cstdint>

// ---------------------------------------------------------------------------
// Int8Linear on GB300 (sm_103a). Exact int8 math on bf16 tensor pipe.
// R15 (from R12 @338us best; R13/R14 warp-spec lost to per-iter issue+sync):
//   TILED OPERANDS + cp.async.bulk: quant/pack write tile-contiguous,
//   SW128-pre-swizzled layouts [tile][kstage][256x128B]. One thread runs the
//   whole mainloop: 2x 32KB bulk copies/stage (mbarrier complete_tx), 8 MMA
//   dispatches, commit. No __syncthreads / wait_group / per-thread LDGSTS.
// ---------------------------------------------------------------------------

#if defined(__CUDA_ARCH__) && (defined(__CUDA_ARCH_FEAT_SM103_ALL) || defined(__CUDA_ARCH_FEAT_SM100_ALL) || defined(__CUDA_ARCH_FEAT_SM101_ALL))
#define HAS_TC 1
#else
#define HAS_TC 0
#endif

#define K_DIM 4096
#define N_DIM 4096
#define MAX_T 8192

#define BM 256                // CTA M tile (2 x 128 subtiles)
#define SM_TILE 128           // MMA M per dispatch
#define BN 256
#define BK_EL 64              // bf16 K elements per stage (128B rows)
#define STAGES 3
#define KSTEPS 4              // BK_EL / 16
#define NIT (K_DIM / BK_EL)   // 64

#define A_SUB_BYTES (SM_TILE * 128)                    // 16384
#define TILE_KS_BYTES 32768u                           // 256 rows x 128B
#define STAGE_BYTES (2 * TILE_KS_BYTES)                // 65536 (A 32K + B 32K)

#define OFF_TMEM   0u
#define OFF_FULL   16u        // full[0..2]
#define OFF_DONE   40u        // done[0..2]
#define OFF_WS     1024u
#define OFF_BIAS   2048u
#define OFF_STAGE  4096u
#define SMEM_TOTAL (OFF_STAGE + STAGES * STAGE_BYTES)  // 200704

// scratch (allocation-free rule: device globals) — TILED layouts:
//  g_qx_t: [bm(32)][ks(64)][sub(2)][128 rows][128B]  (SW128 pre-applied)
//  g_wb_t: [bn(16)][ks(64)][256 rows][128B]          (SW128 pre-applied)
__device__ __nv_bfloat16 g_qx_t[(size_t)MAX_T * K_DIM];
__device__ float         g_xscale[MAX_T];
__device__ __nv_bfloat16 g_wb_t[(size_t)N_DIM * K_DIM];
__device__ int           g_w_is_int32;

#define SW128(off) ((off) ^ (((off) >> 3) & 0x70))

// ---------------------------------------------------------------------------
__device__ __forceinline__ uint32_t smem_u32(const void* p) {
    return (uint32_t)__cvta_generic_to_shared(p);
}
__device__ __forceinline__ uint32_t pack_bf16x2(float a, float b) {
    __nv_bfloat162 h = __floats2bfloat162_rn(a, b);
    return *reinterpret_cast<uint32_t*>(&h);
}

// ---------------------------------------------------------------------------
__global__ void detect_kernel(const int* __restrict__ w) {
    if (threadIdx.x == 0 && blockIdx.x == 0) {
        int ok = 1;
#pragma unroll
        for (int i = 0; i < 64; ++i) {
            int v = w[i];
            if (v < -200 || v > 200) ok = 0;
        }
        g_w_is_int32 = ok;
    }
}

// weight -> tiled, swizzled bf16. idx indexes 4 consecutive K elements.
__global__ void pack_kernel(const void* __restrict__ w) {
    const size_t idx = (size_t)blockIdx.x * blockDim.x + threadIdx.x;
    float f0, f1, f2, f3;
    if (g_w_is_int32) {
        const int4 v = reinterpret_cast<const int4*>(w)[idx];
        f0 = (float)v.x; f1 = (float)v.y; f2 = (float)v.z; f3 = (float)v.w;
    } else {
        const uint32_t p = reinterpret_cast<const uint32_t*>(w)[idx];
        f0 = (float)(int)(int8_t)(p & 0xff);
        f1 = (float)(int)(int8_t)((p >> 8) & 0xff);
        f2 = (float)(int)(int8_t)((p >> 16) & 0xff);
        f3 = (float)(int)(int8_t)(p >> 24);
    }
    uint2 o;
    o.x = pack_bf16x2(f0, f1);
    o.y = pack_bf16x2(f2, f3);

    const size_t e = idx * 4;
    const int n  = (int)(e >> 12);          // / K_DIM
    const int k  = (int)(e & 4095);
    const int ks = k >> 6, kl = k & 63;
    const int bn = n >> 8, r = n & 255;
    const size_t dst = (size_t)(bn * 64 + ks) * TILE_KS_BYTES
                     + SW128((uint32_t)(r * 128 + kl * 2));
    *reinterpret_cast<uint2*>(reinterpret_cast<char*>(g_wb_t) + dst) = o;
}

// ---------------------------------------------------------------------------
__global__ void quant_kernel(const float* __restrict__ x) {
    const int row = blockIdx.x;
    const int t   = threadIdx.x;
    const float* xr = x + (size_t)row * K_DIM;

    float4 v[4];
    float amax = 0.f;
#pragma unroll
    for (int i = 0; i < 4; ++i) {
        v[i] = reinterpret_cast<const float4*>(xr)[t + i * 256];
        amax = fmaxf(amax, fmaxf(fmaxf(fabsf(v[i].x), fabsf(v[i].y)),
                                 fmaxf(fabsf(v[i].z), fabsf(v[i].w))));
    }

    __shared__ float smax[8];
#pragma unroll
    for (int o = 16; o > 0; o >>= 1)
        amax = fmaxf(amax, __shfl_xor_sync(0xffffffffu, amax, o));
    if ((t & 31) == 0) smax[t >> 5] = amax;
    __syncthreads();
    if (t < 32) {
        float m = (t < 8) ? smax[t] : 0.f;
#pragma unroll
        for (int o = 4; o > 0; o >>= 1)
            m = fmaxf(m, __shfl_xor_sync(0xffffffffu, m, o));
        if (t == 0) smax[0] = m;
    }
    __syncthreads();

    const float scale = smax[0] / 127.0f;
    if (t == 0) g_xscale[row] = scale;
    const float sdiv = (scale > 0.f) ? scale : 1.f;

    const int bm = row >> 8, r = row & 255;
    const int sub = r >> 7, lr = r & 127;
    char* dst_base = reinterpret_cast<char*>(g_qx_t)
                   + (size_t)bm * 64 * TILE_KS_BYTES
                   + (size_t)sub * A_SUB_BYTES;

#pragma unroll
    for (int i = 0; i < 4; ++i) {
        float f[4] = {v[i].x, v[i].y, v[i].z, v[i].w};
#pragma unroll
        for (int j = 0; j < 4; ++j) {
            float q = rintf(f[j] / sdiv);
            f[j] = fminf(fmaxf(q, -127.f), 127.f);
        }
        uint2 o;
        o.x = pack_bf16x2(f[0], f[1]);
        o.y = pack_bf16x2(f[2], f[3]);
        const int eb = (t + i * 256) * 4;       // element offset in row
        const int ks = eb >> 6, kl = eb & 63;
        *reinterpret_cast<uint2*>(dst_base + (size_t)ks * TILE_KS_BYTES
                                  + SW128((uint32_t)(lr * 128 + kl * 2))) = o;
    }
}

// ===========================================================================
// tcgen05 kind::f16 GEMM (sm_103a cubin)
// ===========================================================================
#if HAS_TC
__device__ __forceinline__ void mbar_init(uint32_t a, uint32_t cnt) {
    asm volatile("mbarrier.init.shared.b64 [%0], %1;" :: "r"(a), "r"(cnt) : "memory");
}
__device__ __forceinline__ void mbar_expect_tx(uint32_t a, uint32_t bytes) {
    asm volatile("mbarrier.arrive.expect_tx.shared.b64 _, [%0], %1;"
                 :: "r"(a), "r"(bytes) : "memory");
}
__device__ __forceinline__ void mbar_wait(uint32_t a, uint32_t parity) {
    asm volatile(
        "{\n\t.reg .pred P;\n\t"
        "W_%=:\n\t"
        "mbarrier.try_wait.parity.acquire.cta.shared::cta.b64 P, [%0], %1, 0x989680;\n\t"
        "@!P bra W_%=;\n\t}"
        :: "r"(a), "r"(parity) : "memory");
}
__device__ __forceinline__ void tc_commit(uint32_t bar) {
    asm volatile(
        "tcgen05.commit.cta_group::1.mbarrier::arrive::one.shared::cluster.b64 [%0];"
        :: "r"(bar) : "memory");
}
__device__ __forceinline__ void bulk_g2s(uint32_t dst, const void* src,
                                         uint32_t bytes, uint32_t mbar) {
    asm volatile(
        "cp.async.bulk.shared::cta.global.mbarrier::complete_tx::bytes "
        "[%0], [%1], %2, [%3];"
        :: "r"(dst), "l"(src), "r"(bytes), "r"(mbar) : "memory");
}
__device__ __forceinline__ uint64_t make_desc_sw128(uint32_t base) {
    const uint64_t DESC_BASE =
        (uint64_t(2)  << 61) | (uint64_t(1) << 46) |
        (uint64_t(64) << 32) | (uint64_t(1) << 16);
    return DESC_BASE | ((uint64_t)(base >> 4) & 0x3FFF);
}
// kind::f16 idesc: F32@4, BF16@7, BF16@10, N-field [16:23)=N/4, M-field=(M>>4)<<24
#define MMA_IDESC ((1u << 4) | (1u << 7) | (1u << 10) | ((BN / 4) << 16) | ((SM_TILE >> 4) << 24))

__device__ __forceinline__ void mma_f16_ss(uint32_t d_tmem, uint64_t a_desc,
                                           uint64_t b_desc, uint32_t en) {
    asm volatile(
        "{\n\t.reg .pred p;\n\t"
        "setp.ne.u32 p, %5, 0;\n\t"
        "tcgen05.mma.cta_group::1.kind::f16 [%0], %1, %2, %3, {%4, %4, %4, %4}, p;\n\t}"
        :: "r"(d_tmem), "l"(a_desc), "l"(b_desc), "r"(MMA_IDESC), "r"(0u), "r"(en)
        : "memory");
}
#endif  // HAS_TC

#if HAS_TC
__global__ void __launch_bounds__(128) __cluster_dims__(1, 1, 1)
#else
__global__ void __launch_bounds__(128)
#endif
gemm_tc(const float* __restrict__ wscale,
        const float* __restrict__ bias,
        float* __restrict__ out) {
#if HAS_TC
    extern __shared__ char smem[];
    const uint32_t sb = smem_u32(smem);
    const int bn = blockIdx.x, bm = blockIdx.y;
    const int tid = threadIdx.x, wid = tid >> 5, lane = tid & 31;

    // warp 0 allocs 512 TMEM cols; no relinquish (R9 fix)
    if (wid == 0) {
        asm volatile("tcgen05.alloc.cta_group::1.sync.aligned.shared::cta.b32 [%0], %1;"
                     :: "r"(sb + OFF_TMEM), "r"(512u) : "memory");
    }

    if (tid == 0) {
#pragma unroll
        for (int s = 0; s < STAGES; ++s) {
            mbar_init(sb + OFF_FULL + 8 * s, 1);   // expect_tx tracks data
            mbar_init(sb + OFF_DONE + 8 * s, 1);   // one tcgen05.commit
        }
    }
#pragma unroll
    for (int i = tid; i < BN; i += 128) {
        const int n0 = bn * BN;
        ((float*)(smem + OFF_WS))[i]   = wscale[n0 + i];
        ((float*)(smem + OFF_BIAS))[i] = bias[n0 + i];
    }
    __syncthreads();

    uint32_t tmem;
    asm volatile("ld.shared.b32 %0, [%1];" : "=r"(tmem) : "r"(sb + OFF_TMEM));

    // tile-contiguous sources: 32KB per (tile, kstage)
    const char* Asrc = reinterpret_cast<const char*>(g_qx_t)
                     + (size_t)bm * 64 * TILE_KS_BYTES;
    const char* Bsrc = reinterpret_cast<const char*>(g_wb_t)
                     + (size_t)bn * 64 * TILE_KS_BYTES;

    if (tid == 0) {
        // ============ SINGLE-THREAD MAINLOOP ============
        // issue loads for a stage: 2 bulk copies + expect_tx
#define ISSUE_STAGE(S)                                                          \
        do {                                                                    \
            const int _b = (S) % STAGES;                                        \
            const uint32_t _dst = sb + OFF_STAGE + _b * STAGE_BYTES;            \
            const uint32_t _fb  = sb + OFF_FULL + 8 * _b;                       \
            mbar_expect_tx(_fb, STAGE_BYTES);                                   \
            bulk_g2s(_dst,                 Asrc + (size_t)(S) * TILE_KS_BYTES,  \
                     TILE_KS_BYTES, _fb);                                       \
            bulk_g2s(_dst + TILE_KS_BYTES, Bsrc + (size_t)(S) * TILE_KS_BYTES,  \
                     TILE_KS_BYTES, _fb);                                       \
        } while (0)

        ISSUE_STAGE(0);
        ISSUE_STAGE(1);
        ISSUE_STAGE(2);

        for (int it = 0; it < NIT; ++it) {
            const int b = it % STAGES;
            mbar_wait(sb + OFF_FULL + 8 * b, (it / STAGES) & 1);
            asm volatile("fence.proxy.async.shared::cta;" ::: "memory");

            const uint32_t base = sb + OFF_STAGE + b * STAGE_BYTES;
            const uint64_t a0d = make_desc_sw128(base);
            const uint64_t a1d = make_desc_sw128(base + A_SUB_BYTES);
            const uint64_t bd  = make_desc_sw128(base + TILE_KS_BYTES);
            const uint32_t en0 = (it > 0) ? 1u : 0u;
#pragma unroll
            for (int k = 0; k < KSTEPS; ++k) {        // K=16 step -> +2 desc units
                const uint32_t en = (k > 0) ? 1u : en0;
                mma_f16_ss(tmem,       a0d + k * 2, bd + k * 2, en);
                mma_f16_ss(tmem + 256, a1d + k * 2, bd + k * 2, en);
            }
            tc_commit(sb + OFF_DONE + 8 * b);

            const int pf = it + STAGES;
            if (pf < NIT) {
                // buffer b reused by stage pf: MMA(it) on it must complete
                mbar_wait(sb + OFF_DONE + 8 * b, (it / STAGES) & 1);
                ISSUE_STAGE(pf);
            }
        }
        // final MMA completion (stages NIT-3..NIT-1 not yet waited; the last
        // commit covers all prior MMAs in order -> wait only the last)
        mbar_wait(sb + OFF_DONE + 8 * ((NIT - 1) % STAGES),
                  ((NIT - 1) / STAGES) & 1);
    }

    __syncthreads();   // thread 0 verified all MMAs complete

    // ---- epilogue: fp32 TMEM (2 subtiles) -> dequant -> gmem ----
    asm volatile("tcgen05.fence::after_thread_sync;" ::: "memory");

    const float* wsS = (const float*)(smem + OFF_WS);
    const float* bS  = (const float*)(smem + OFF_BIAS);

#pragma unroll
    for (int sub = 0; sub < 2; ++sub) {
        const int m = bm * BM + sub * SM_TILE + wid * 32 + lane;
        const float xs = g_xscale[m];
        float* orow = out + (size_t)m * N_DIM + bn * BN;
        const uint32_t dbase = tmem + sub * 256;

#pragma unroll
        for (int ch = 0; ch < BN / 32; ++ch) {
            uint32_t r[32];
            asm volatile(
                "tcgen05.ld.sync.aligned.32x32b.x32.b32 "
                "{%0, %1, %2, %3, %4, %5, %6, %7, "
                " %8, %9, %10, %11, %12, %13, %14, %15, "
                " %16, %17, %18, %19, %20, %21, %22, %23, "
                " %24, %25, %26, %27, %28, %29, %30, %31}, [%32];"
                : "=r"(r[0]),  "=r"(r[1]),  "=r"(r[2]),  "=r"(r[3]),
                  "=r"(r[4]),  "=r"(r[5]),  "=r"(r[6]),  "=r"(r[7]),
                  "=r"(r[8]),  "=r"(r[9]),  "=r"(r[10]), "=r"(r[11]),
                  "=r"(r[12]), "=r"(r[13]), "=r"(r[14]), "=r"(r[15]),
                  "=r"(r[16]), "=r"(r[17]), "=r"(r[18]), "=r"(r[19]),
                  "=r"(r[20]), "=r"(r[21]), "=r"(r[22]), "=r"(r[23]),
                  "=r"(r[24]), "=r"(r[25]), "=r"(r[26]), "=r"(r[27]),
                  "=r"(r[28]), "=r"(r[29]), "=r"(r[30]), "=r"(r[31])
                : "r"(dbase + ch * 32));
            asm volatile("tcgen05.wait::ld.sync.aligned;" ::: "memory");

#pragma unroll
            for (int q = 0; q < 8; ++q) {
                const int c = ch * 32 + q * 4;
                float4 v;
                v.x = __uint_as_float(r[q * 4 + 0]) * wsS[c + 0] * xs + bS[c + 0];
                v.y = __uint_as_float(r[q * 4 + 1]) * wsS[c + 1] * xs + bS[c + 1];
                v.z = __uint_as_float(r[q * 4 + 2]) * wsS[c + 2] * xs + bS[c + 2];
                v.w = __uint_as_float(r[q * 4 + 3]) * wsS[c + 3] * xs + bS[c + 3];
                *reinterpret_cast<float4*>(orow + c) = v;
            }
        }
    }

    __syncthreads();
    if (tid == 0) {
#pragma unroll
        for (int s = 0; s < STAGES; ++s) {
            asm volatile("mbarrier.inval.shared.b64 [%0];"
                         :: "r"(sb + OFF_FULL + 8 * s) : "memory");
            asm volatile("mbarrier.inval.shared.b64 [%0];"
                         :: "r"(sb + OFF_DONE + 8 * s) : "memory");
        }
    }
    __syncthreads();
    if (wid == 0) {
        asm volatile("tcgen05.dealloc.cta_group::1.sync.aligned.b32 %0, %1;"
                     :: "r"(tmem), "r"(512u));
    }
#endif  // HAS_TC
}

// ---------------------------------------------------------------------------
extern "C" void kernel_launch(void* const* d_in, const int* in_sizes, int n_in,
                              void* d_out, int out_size) {
    const float* x      = (const float*)d_in[0];
    const void*  weight = d_in[1];
    const float* wscale = (const float*)d_in[2];
    const float* bias   = (const float*)d_in[3];
    float* out = (float*)d_out;

    const int T = in_sizes[0] / K_DIM;   // 8192

    cudaFuncSetAttribute(gemm_tc, cudaFuncAttributeMaxDynamicSharedMemorySize,
                         SMEM_TOTAL);

    detect_kernel<<<1, 32>>>((const int*)weight);
    pack_kernel<<<(N_DIM * K_DIM / 4) / 256, 256>>>(weight);
    quant_kernel<<<T, 256>>>(x);

    dim3 grid_tc(N_DIM / BN, T / BM);   // (16, 32) = 512 CTAs
    gemm_tc<<<grid_tc, 128, SMEM_TOTAL>>>(wscale, bias, out);
}

// round 16
// speedup vs baseline: 1.9072x; 1.2315x over previous
#include <cuda_runtime.h>
#include <cuda_bf16.h>
#include <cstdint>

// ---------------------------------------------------------------------------
// Int8Linear on GB300 (sm_103a). Exact int8 math on bf16 tensor pipe.
// R16 (from R15 @308us, gemm 259us, done-wait serialized in mainloop):
//   TWO single-thread roles: warp0 thread = MMA issuer (wait full -> 8 MMA ->
//   commit), warp1 thread = loader (wait done(S-3) -> 2 bulk copies). The MMA
//   thread never blocks on MMA completion; tcgen05 queue paces it.
//   Tiled SW128-pre-swizzled operands + cp.async.bulk (R15).
// ---------------------------------------------------------------------------

#if defined(__CUDA_ARCH__) && (defined(__CUDA_ARCH_FEAT_SM103_ALL) || defined(__CUDA_ARCH_FEAT_SM100_ALL) || defined(__CUDA_ARCH_FEAT_SM101_ALL))
#define HAS_TC 1
#else
#define HAS_TC 0
#endif

#define K_DIM 4096
#define N_DIM 4096
#define MAX_T 8192

#define BM 256                // CTA M tile (2 x 128 subtiles)
#define SM_TILE 128           // MMA M per dispatch
#define BN 256
#define BK_EL 64              // bf16 K elements per stage (128B rows)
#define STAGES 3
#define KSTEPS 4              // BK_EL / 16
#define NIT (K_DIM / BK_EL)   // 64

#define A_SUB_BYTES (SM_TILE * 128)                    // 16384
#define TILE_KS_BYTES 32768u                           // 256 rows x 128B
#define STAGE_BYTES (2 * TILE_KS_BYTES)                // 65536 (A 32K + B 32K)

#define OFF_TMEM   0u
#define OFF_FULL   16u        // full[0..2]
#define OFF_DONE   40u        // done[0..2]
#define OFF_WS     1024u
#define OFF_BIAS   2048u
#define OFF_STAGE  4096u
#define SMEM_TOTAL (OFF_STAGE + STAGES * STAGE_BYTES)  // 200704

// scratch (allocation-free rule: device globals) — TILED layouts:
//  g_qx_t: [bm(32)][ks(64)][sub(2)][128 rows][128B]  (SW128 pre-applied)
//  g_wb_t: [bn(16)][ks(64)][256 rows][128B]          (SW128 pre-applied)
__device__ __nv_bfloat16 g_qx_t[(size_t)MAX_T * K_DIM];
__device__ float         g_xscale[MAX_T];
__device__ __nv_bfloat16 g_wb_t[(size_t)N_DIM * K_DIM];
__device__ int           g_w_is_int32;

#define SW128(off) ((off) ^ (((off) >> 3) & 0x70))

// ---------------------------------------------------------------------------
__device__ __forceinline__ uint32_t smem_u32(const void* p) {
    return (uint32_t)__cvta_generic_to_shared(p);
}
__device__ __forceinline__ uint32_t pack_bf16x2(float a, float b) {
    __nv_bfloat162 h = __floats2bfloat162_rn(a, b);
    return *reinterpret_cast<uint32_t*>(&h);
}

// ---------------------------------------------------------------------------
__global__ void detect_kernel(const int* __restrict__ w) {
    if (threadIdx.x == 0 && blockIdx.x == 0) {
        int ok = 1;
#pragma unroll
        for (int i = 0; i < 64; ++i) {
            int v = w[i];
            if (v < -200 || v > 200) ok = 0;
        }
        g_w_is_int32 = ok;
    }
}

// weight -> tiled, swizzled bf16. idx indexes 4 consecutive K elements.
__global__ void pack_kernel(const void* __restrict__ w) {
    const size_t idx = (size_t)blockIdx.x * blockDim.x + threadIdx.x;
    float f0, f1, f2, f3;
    if (g_w_is_int32) {
        const int4 v = reinterpret_cast<const int4*>(w)[idx];
        f0 = (float)v.x; f1 = (float)v.y; f2 = (float)v.z; f3 = (float)v.w;
    } else {
        const uint32_t p = reinterpret_cast<const uint32_t*>(w)[idx];
        f0 = (float)(int)(int8_t)(p & 0xff);
        f1 = (float)(int)(int8_t)((p >> 8) & 0xff);
        f2 = (float)(int)(int8_t)((p >> 16) & 0xff);
        f3 = (float)(int)(int8_t)(p >> 24);
    }
    uint2 o;
    o.x = pack_bf16x2(f0, f1);
    o.y = pack_bf16x2(f2, f3);

    const size_t e = idx * 4;
    const int n  = (int)(e >> 12);          // / K_DIM
    const int k  = (int)(e & 4095);
    const int ks = k >> 6, kl = k & 63;
    const int bn = n >> 8, r = n & 255;
    const size_t dst = (size_t)(bn * 64 + ks) * TILE_KS_BYTES
                     + SW128((uint32_t)(r * 128 + kl * 2));
    *reinterpret_cast<uint2*>(reinterpret_cast<char*>(g_wb_t) + dst) = o;
}

// ---------------------------------------------------------------------------
__global__ void quant_kernel(const float* __restrict__ x) {
    const int row = blockIdx.x;
    const int t   = threadIdx.x;
    const float* xr = x + (size_t)row * K_DIM;

    float4 v[4];
    float amax = 0.f;
#pragma unroll
    for (int i = 0; i < 4; ++i) {
        v[i] = reinterpret_cast<const float4*>(xr)[t + i * 256];
        amax = fmaxf(amax, fmaxf(fmaxf(fabsf(v[i].x), fabsf(v[i].y)),
                                 fmaxf(fabsf(v[i].z), fabsf(v[i].w))));
    }

    __shared__ float smax[8];
#pragma unroll
    for (int o = 16; o > 0; o >>= 1)
        amax = fmaxf(amax, __shfl_xor_sync(0xffffffffu, amax, o));
    if ((t & 31) == 0) smax[t >> 5] = amax;
    __syncthreads();
    if (t < 32) {
        float m = (t < 8) ? smax[t] : 0.f;
#pragma unroll
        for (int o = 4; o > 0; o >>= 1)
            m = fmaxf(m, __shfl_xor_sync(0xffffffffu, m, o));
        if (t == 0) smax[0] = m;
    }
    __syncthreads();

    const float scale = smax[0] / 127.0f;
    if (t == 0) g_xscale[row] = scale;
    const float sdiv = (scale > 0.f) ? scale : 1.f;

    const int bm = row >> 8, r = row & 255;
    const int sub = r >> 7, lr = r & 127;
    char* dst_base = reinterpret_cast<char*>(g_qx_t)
                   + (size_t)bm * 64 * TILE_KS_BYTES
                   + (size_t)sub * A_SUB_BYTES;

#pragma unroll
    for (int i = 0; i < 4; ++i) {
        float f[4] = {v[i].x, v[i].y, v[i].z, v[i].w};
#pragma unroll
        for (int j = 0; j < 4; ++j) {
            float q = rintf(f[j] / sdiv);
            f[j] = fminf(fmaxf(q, -127.f), 127.f);
        }
        uint2 o;
        o.x = pack_bf16x2(f[0], f[1]);
        o.y = pack_bf16x2(f[2], f[3]);
        const int eb = (t + i * 256) * 4;       // element offset in row
        const int ks = eb >> 6, kl = eb & 63;
        *reinterpret_cast<uint2*>(dst_base + (size_t)ks * TILE_KS_BYTES
                                  + SW128((uint32_t)(lr * 128 + kl * 2))) = o;
    }
}

// ===========================================================================
// tcgen05 kind::f16 GEMM (sm_103a cubin)
// ===========================================================================
#if HAS_TC
__device__ __forceinline__ void mbar_init(uint32_t a, uint32_t cnt) {
    asm volatile("mbarrier.init.shared.b64 [%0], %1;" :: "r"(a), "r"(cnt) : "memory");
}
__device__ __forceinline__ void mbar_expect_tx(uint32_t a, uint32_t bytes) {
    asm volatile("mbarrier.arrive.expect_tx.shared.b64 _, [%0], %1;"
                 :: "r"(a), "r"(bytes) : "memory");
}
__device__ __forceinline__ void mbar_wait(uint32_t a, uint32_t parity) {
    asm volatile(
        "{\n\t.reg .pred P;\n\t"
        "W_%=:\n\t"
        "mbarrier.try_wait.parity.acquire.cta.shared::cta.b64 P, [%0], %1, 0x989680;\n\t"
        "@!P bra W_%=;\n\t}"
        :: "r"(a), "r"(parity) : "memory");
}
__device__ __forceinline__ void tc_commit(uint32_t bar) {
    asm volatile(
        "tcgen05.commit.cta_group::1.mbarrier::arrive::one.shared::cluster.b64 [%0];"
        :: "r"(bar) : "memory");
}
__device__ __forceinline__ void bulk_g2s(uint32_t dst, const void* src,
                                         uint32_t bytes, uint32_t mbar) {
    asm volatile(
        "cp.async.bulk.shared::cta.global.mbarrier::complete_tx::bytes "
        "[%0], [%1], %2, [%3];"
        :: "r"(dst), "l"(src), "r"(bytes), "r"(mbar) : "memory");
}
__device__ __forceinline__ uint64_t make_desc_sw128(uint32_t base) {
    const uint64_t DESC_BASE =
        (uint64_t(2)  << 61) | (uint64_t(1) << 46) |
        (uint64_t(64) << 32) | (uint64_t(1) << 16);
    return DESC_BASE | ((uint64_t)(base >> 4) & 0x3FFF);
}
__device__ __forceinline__ uint32_t elect_one() {
    uint32_t pred;
    asm volatile(
        "{\n\t.reg .pred p;\n\t"
        "elect.sync _|p, 0xFFFFFFFF;\n\t"
        "selp.b32 %0, 1, 0, p;\n\t}"
        : "=r"(pred));
    return pred;
}
// kind::f16 idesc: F32@4, BF16@7, BF16@10, N-field [16:23)=N/4, M-field=(M>>4)<<24
#define MMA_IDESC ((1u << 4) | (1u << 7) | (1u << 10) | ((BN / 4) << 16) | ((SM_TILE >> 4) << 24))

__device__ __forceinline__ void mma_f16_ss(uint32_t d_tmem, uint64_t a_desc,
                                           uint64_t b_desc, uint32_t en) {
    asm volatile(
        "{\n\t.reg .pred p;\n\t"
        "setp.ne.u32 p, %5, 0;\n\t"
        "tcgen05.mma.cta_group::1.kind::f16 [%0], %1, %2, %3, {%4, %4, %4, %4}, p;\n\t}"
        :: "r"(d_tmem), "l"(a_desc), "l"(b_desc), "r"(MMA_IDESC), "r"(0u), "r"(en)
        : "memory");
}
#endif  // HAS_TC

#if HAS_TC
__global__ void __launch_bounds__(128) __cluster_dims__(1, 1, 1)
#else
__global__ void __launch_bounds__(128)
#endif
gemm_tc(const float* __restrict__ wscale,
        const float* __restrict__ bias,
        float* __restrict__ out) {
#if HAS_TC
    extern __shared__ char smem[];
    const uint32_t sb = smem_u32(smem);
    const int bn = blockIdx.x, bm = blockIdx.y;
    const int tid = threadIdx.x, wid = tid >> 5, lane = tid & 31;

    // warp 0 allocs 512 TMEM cols; no relinquish (R9 fix)
    if (wid == 0) {
        asm volatile("tcgen05.alloc.cta_group::1.sync.aligned.shared::cta.b32 [%0], %1;"
                     :: "r"(sb + OFF_TMEM), "r"(512u) : "memory");
    }

    if (tid == 0) {
#pragma unroll
        for (int s = 0; s < STAGES; ++s) {
            mbar_init(sb + OFF_FULL + 8 * s, 1);   // expect_tx tracks data
            mbar_init(sb + OFF_DONE + 8 * s, 1);   // one tcgen05.commit
        }
    }
#pragma unroll
    for (int i = tid; i < BN; i += 128) {
        const int n0 = bn * BN;
        ((float*)(smem + OFF_WS))[i]   = wscale[n0 + i];
        ((float*)(smem + OFF_BIAS))[i] = bias[n0 + i];
    }
    __syncthreads();

    uint32_t tmem;
    asm volatile("ld.shared.b32 %0, [%1];" : "=r"(tmem) : "r"(sb + OFF_TMEM));

    // tile-contiguous sources: 32KB per (tile, kstage)
    const char* Asrc = reinterpret_cast<const char*>(g_qx_t)
                     + (size_t)bm * 64 * TILE_KS_BYTES;
    const char* Bsrc = reinterpret_cast<const char*>(g_wb_t)
                     + (size_t)bn * 64 * TILE_KS_BYTES;

#define ISSUE_STAGE(S)                                                          \
    do {                                                                        \
        const int _b = (S) % STAGES;                                            \
        const uint32_t _dst = sb + OFF_STAGE + _b * STAGE_BYTES;                \
        const uint32_t _fb  = sb + OFF_FULL + 8 * _b;                           \
        mbar_expect_tx(_fb, STAGE_BYTES);                                       \
        bulk_g2s(_dst,                 Asrc + (size_t)(S) * TILE_KS_BYTES,      \
                 TILE_KS_BYTES, _fb);                                           \
        bulk_g2s(_dst + TILE_KS_BYTES, Bsrc + (size_t)(S) * TILE_KS_BYTES,      \
                 TILE_KS_BYTES, _fb);                                           \
    } while (0)

    if (wid == 0) {
        // ============ MMA thread: never blocks on MMA completion ============
        if (elect_one()) {
            for (int it = 0; it < NIT; ++it) {
                const int b = it % STAGES;
                mbar_wait(sb + OFF_FULL + 8 * b, (it / STAGES) & 1);

                const uint32_t base = sb + OFF_STAGE + b * STAGE_BYTES;
                const uint64_t a0d = make_desc_sw128(base);
                const uint64_t a1d = make_desc_sw128(base + A_SUB_BYTES);
                const uint64_t bd  = make_desc_sw128(base + TILE_KS_BYTES);
                const uint32_t en0 = (it > 0) ? 1u : 0u;
#pragma unroll
                for (int k = 0; k < KSTEPS; ++k) {    // K=16 step -> +2 desc units
                    const uint32_t en = (k > 0) ? 1u : en0;
                    mma_f16_ss(tmem,       a0d + k * 2, bd + k * 2, en);
                    mma_f16_ss(tmem + 256, a1d + k * 2, bd + k * 2, en);
                }
                tc_commit(sb + OFF_DONE + 8 * b);
            }
            // final MMA completion (commits are in-order)
            mbar_wait(sb + OFF_DONE + 8 * ((NIT - 1) % STAGES),
                      ((NIT - 1) / STAGES) & 1);
        }
    } else if (wid == 1) {
        // ============ loader thread: trails MMA completion by 3 stages ======
        if (elect_one()) {
            ISSUE_STAGE(0);
            ISSUE_STAGE(1);
            ISSUE_STAGE(2);
            for (int S = STAGES; S < NIT; ++S) {
                const int b = S % STAGES;
                // buffer b reused by stage S: MMA(S-3) on it must be complete
                mbar_wait(sb + OFF_DONE + 8 * b, ((S / STAGES) - 1) & 1);
                ISSUE_STAGE(S);
            }
        }
    }

    __syncthreads();   // MMA thread verified all MMAs complete

    // ---- epilogue: fp32 TMEM (2 subtiles) -> dequant -> gmem ----
    asm volatile("tcgen05.fence::after_thread_sync;" ::: "memory");

    const float* wsS = (const float*)(smem + OFF_WS);
    const float* bS  = (const float*)(smem + OFF_BIAS);

#pragma unroll
    for (int sub = 0; sub < 2; ++sub) {
        const int m = bm * BM + sub * SM_TILE + wid * 32 + lane;
        const float xs = g_xscale[m];
        float* orow = out + (size_t)m * N_DIM + bn * BN;
        const uint32_t dbase = tmem + sub * 256;

#pragma unroll
        for (int ch = 0; ch < BN / 32; ++ch) {
            uint32_t r[32];
            asm volatile(
                "tcgen05.ld.sync.aligned.32x32b.x32.b32 "
                "{%0, %1, %2, %3, %4, %5, %6, %7, "
                " %8, %9, %10, %11, %12, %13, %14, %15, "
                " %16, %17, %18, %19, %20, %21, %22, %23, "
                " %24, %25, %26, %27, %28, %29, %30, %31}, [%32];"
                : "=r"(r[0]),  "=r"(r[1]),  "=r"(r[2]),  "=r"(r[3]),
                  "=r"(r[4]),  "=r"(r[5]),  "=r"(r[6]),  "=r"(r[7]),
                  "=r"(r[8]),  "=r"(r[9]),  "=r"(r[10]), "=r"(r[11]),
                  "=r"(r[12]), "=r"(r[13]), "=r"(r[14]), "=r"(r[15]),
                  "=r"(r[16]), "=r"(r[17]), "=r"(r[18]), "=r"(r[19]),
                  "=r"(r[20]), "=r"(r[21]), "=r"(r[22]), "=r"(r[23]),
                  "=r"(r[24]), "=r"(r[25]), "=r"(r[26]), "=r"(r[27]),
                  "=r"(r[28]), "=r"(r[29]), "=r"(r[30]), "=r"(r[31])
                : "r"(dbase + ch * 32));
            asm volatile("tcgen05.wait::ld.sync.aligned;" ::: "memory");

#pragma unroll
            for (int q = 0; q < 8; ++q) {
                const int c = ch * 32 + q * 4;
                float4 v;
                v.x = __uint_as_float(r[q * 4 + 0]) * wsS[c + 0] * xs + bS[c + 0];
                v.y = __uint_as_float(r[q * 4 + 1]) * wsS[c + 1] * xs + bS[c + 1];
                v.z = __uint_as_float(r[q * 4 + 2]) * wsS[c + 2] * xs + bS[c + 2];
                v.w = __uint_as_float(r[q * 4 + 3]) * wsS[c + 3] * xs + bS[c + 3];
                *reinterpret_cast<float4*>(orow + c) = v;
            }
        }
    }

    __syncthreads();
    if (tid == 0) {
#pragma unroll
        for (int s = 0; s < STAGES; ++s) {
            asm volatile("mbarrier.inval.shared.b64 [%0];"
                         :: "r"(sb + OFF_FULL + 8 * s) : "memory");
            asm volatile("mbarrier.inval.shared.b64 [%0];"
                         :: "r"(sb + OFF_DONE + 8 * s) : "memory");
        }
    }
    __syncthreads();
    if (wid == 0) {
        asm volatile("tcgen05.dealloc.cta_group::1.sync.aligned.b32 %0, %1;"
                     :: "r"(tmem), "r"(512u));
    }
#endif  // HAS_TC
}

// ---------------------------------------------------------------------------
extern "C" void kernel_launch(void* const* d_in, const int* in_sizes, int n_in,
                              void* d_out, int out_size) {
    const float* x      = (const float*)d_in[0];
    const void*  weight = d_in[1];
    const float* wscale = (const float*)d_in[2];
    const float* bias   = (const float*)d_in[3];
    float* out = (float*)d_out;

    const int T = in_sizes[0] / K_DIM;   // 8192

    cudaFuncSetAttribute(gemm_tc, cudaFuncAttributeMaxDynamicSharedMemorySize,
                         SMEM_TOTAL);

    detect_kernel<<<1, 32>>>((const int*)weight);
    pack_kernel<<<(N_DIM * K_DIM / 4) / 256, 256>>>(weight);
    quant_kernel<<<T, 256>>>(x);

    dim3 grid_tc(N_DIM / BN, T / BM);   // (16, 32) = 512 CTAs
    gemm_tc<<<grid_tc, 128, SMEM_TOTAL>>>(wscale, bias, out);
}

// round 17
// speedup vs baseline: 1.9369x; 1.0156x over previous
#include <cuda_runtime.h>
#include <cuda_bf16.h>
#include <cstdint>

// ---------------------------------------------------------------------------
// Int8Linear on GB300 (sm_103a). Exact int8 math on bf16 tensor pipe.
// R17 (from R16 @250us, gemm 199us, tensor 57%):
//   PERSISTENT CTAs (grid=148, 3-4 tiles each) + cross-tile prefetch.
//   Warps 0-3: MMA issue (warp0 elected) + epilogue, bracketed by
//   bar.sync 1,128. Warp 4: loader thread, never blocked by epilogue ->
//   next tile's stages stream in during the current epilogue.
//   Global stage counter g keeps full/done parity continuous across tiles.
// ---------------------------------------------------------------------------

#if defined(__CUDA_ARCH__) && (defined(__CUDA_ARCH_FEAT_SM103_ALL) || defined(__CUDA_ARCH_FEAT_SM100_ALL) || defined(__CUDA_ARCH_FEAT_SM101_ALL))
#define HAS_TC 1
#else
#define HAS_TC 0
#endif

#define K_DIM 4096
#define N_DIM 4096
#define MAX_T 8192

#define BM 256                // CTA M tile (2 x 128 subtiles)
#define SM_TILE 128           // MMA M per dispatch
#define BN 256
#define BK_EL 64              // bf16 K per stage (128B rows)
#define STAGES 3
#define KSTEPS 4              // BK_EL / 16
#define NIT (K_DIM / BK_EL)   // 64
#define NTILES ((N_DIM / BN) * (MAX_T / BM))   // 16 x 32 = 512
#define GRID 148

#define A_SUB_BYTES (SM_TILE * 128)                    // 16384
#define TILE_KS_BYTES 32768u                           // 256 rows x 128B
#define STAGE_BYTES (2 * TILE_KS_BYTES)                // 65536

#define OFF_TMEM   0u
#define OFF_FULL   16u        // full[0..2]
#define OFF_DONE   40u        // done[0..2]
#define OFF_WS     1024u
#define OFF_BIAS   2048u
#define OFF_STAGE  4096u
#define SMEM_TOTAL (OFF_STAGE + STAGES * STAGE_BYTES)  // 200704

// scratch (allocation-free rule: device globals) — TILED layouts:
//  g_qx_t: [bm(32)][ks(64)][sub(2)][128 rows][128B]  (SW128 pre-applied)
//  g_wb_t: [bn(16)][ks(64)][256 rows][128B]          (SW128 pre-applied)
__device__ __nv_bfloat16 g_qx_t[(size_t)MAX_T * K_DIM];
__device__ float         g_xscale[MAX_T];
__device__ __nv_bfloat16 g_wb_t[(size_t)N_DIM * K_DIM];
__device__ int           g_w_is_int32;

#define SW128(off) ((off) ^ (((off) >> 3) & 0x70))

// ---------------------------------------------------------------------------
__device__ __forceinline__ uint32_t smem_u32(const void* p) {
    return (uint32_t)__cvta_generic_to_shared(p);
}
__device__ __forceinline__ uint32_t pack_bf16x2(float a, float b) {
    __nv_bfloat162 h = __floats2bfloat162_rn(a, b);
    return *reinterpret_cast<uint32_t*>(&h);
}

// ---------------------------------------------------------------------------
__global__ void detect_kernel(const int* __restrict__ w) {
    if (threadIdx.x == 0 && blockIdx.x == 0) {
        int ok = 1;
#pragma unroll
        for (int i = 0; i < 64; ++i) {
            int v = w[i];
            if (v < -200 || v > 200) ok = 0;
        }
        g_w_is_int32 = ok;
    }
}

__global__ void pack_kernel(const void* __restrict__ w) {
    const size_t idx = (size_t)blockIdx.x * blockDim.x + threadIdx.x;
    float f0, f1, f2, f3;
    if (g_w_is_int32) {
        const int4 v = reinterpret_cast<const int4*>(w)[idx];
        f0 = (float)v.x; f1 = (float)v.y; f2 = (float)v.z; f3 = (float)v.w;
    } else {
        const uint32_t p = reinterpret_cast<const uint32_t*>(w)[idx];
        f0 = (float)(int)(int8_t)(p & 0xff);
        f1 = (float)(int)(int8_t)((p >> 8) & 0xff);
        f2 = (float)(int)(int8_t)((p >> 16) & 0xff);
        f3 = (float)(int)(int8_t)(p >> 24);
    }
    uint2 o;
    o.x = pack_bf16x2(f0, f1);
    o.y = pack_bf16x2(f2, f3);

    const size_t e = idx * 4;
    const int n  = (int)(e >> 12);
    const int k  = (int)(e & 4095);
    const int ks = k >> 6, kl = k & 63;
    const int bn = n >> 8, r = n & 255;
    const size_t dst = (size_t)(bn * 64 + ks) * TILE_KS_BYTES
                     + SW128((uint32_t)(r * 128 + kl * 2));
    *reinterpret_cast<uint2*>(reinterpret_cast<char*>(g_wb_t) + dst) = o;
}

// ---------------------------------------------------------------------------
__global__ void quant_kernel(const float* __restrict__ x) {
    const int row = blockIdx.x;
    const int t   = threadIdx.x;
    const float* xr = x + (size_t)row * K_DIM;

    float4 v[4];
    float amax = 0.f;
#pragma unroll
    for (int i = 0; i < 4; ++i) {
        v[i] = reinterpret_cast<const float4*>(xr)[t + i * 256];
        amax = fmaxf(amax, fmaxf(fmaxf(fabsf(v[i].x), fabsf(v[i].y)),
                                 fmaxf(fabsf(v[i].z), fabsf(v[i].w))));
    }

    __shared__ float smax[8];
#pragma unroll
    for (int o = 16; o > 0; o >>= 1)
        amax = fmaxf(amax, __shfl_xor_sync(0xffffffffu, amax, o));
    if ((t & 31) == 0) smax[t >> 5] = amax;
    __syncthreads();
    if (t < 32) {
        float m = (t < 8) ? smax[t] : 0.f;
#pragma unroll
        for (int o = 4; o > 0; o >>= 1)
            m = fmaxf(m, __shfl_xor_sync(0xffffffffu, m, o));
        if (t == 0) smax[0] = m;
    }
    __syncthreads();

    const float scale = smax[0] / 127.0f;
    if (t == 0) g_xscale[row] = scale;
    const float sdiv = (scale > 0.f) ? scale : 1.f;

    const int bm = row >> 8, r = row & 255;
    const int sub = r >> 7, lr = r & 127;
    char* dst_base = reinterpret_cast<char*>(g_qx_t)
                   + (size_t)bm * 64 * TILE_KS_BYTES
                   + (size_t)sub * A_SUB_BYTES;

#pragma unroll
    for (int i = 0; i < 4; ++i) {
        float f[4] = {v[i].x, v[i].y, v[i].z, v[i].w};
#pragma unroll
        for (int j = 0; j < 4; ++j) {
            float q = rintf(f[j] / sdiv);
            f[j] = fminf(fmaxf(q, -127.f), 127.f);
        }
        uint2 o;
        o.x = pack_bf16x2(f[0], f[1]);
        o.y = pack_bf16x2(f[2], f[3]);
        const int eb = (t + i * 256) * 4;
        const int ks = eb >> 6, kl = eb & 63;
        *reinterpret_cast<uint2*>(dst_base + (size_t)ks * TILE_KS_BYTES
                                  + SW128((uint32_t)(lr * 128 + kl * 2))) = o;
    }
}

// ===========================================================================
// tcgen05 kind::f16 GEMM (sm_103a cubin)
// ===========================================================================
#if HAS_TC
__device__ __forceinline__ void mbar_init(uint32_t a, uint32_t cnt) {
    asm volatile("mbarrier.init.shared.b64 [%0], %1;" :: "r"(a), "r"(cnt) : "memory");
}
__device__ __forceinline__ void mbar_expect_tx(uint32_t a, uint32_t bytes) {
    asm volatile("mbarrier.arrive.expect_tx.shared.b64 _, [%0], %1;"
                 :: "r"(a), "r"(bytes) : "memory");
}
__device__ __forceinline__ void mbar_wait(uint32_t a, uint32_t parity) {
    asm volatile(
        "{\n\t.reg .pred P;\n\t"
        "W_%=:\n\t"
        "mbarrier.try_wait.parity.acquire.cta.shared::cta.b64 P, [%0], %1, 0x989680;\n\t"
        "@!P bra W_%=;\n\t}"
        :: "r"(a), "r"(parity) : "memory");
}
__device__ __forceinline__ void tc_commit(uint32_t bar) {
    asm volatile(
        "tcgen05.commit.cta_group::1.mbarrier::arrive::one.shared::cluster.b64 [%0];"
        :: "r"(bar) : "memory");
}
__device__ __forceinline__ void bulk_g2s(uint32_t dst, const void* src,
                                         uint32_t bytes, uint32_t mbar) {
    asm volatile(
        "cp.async.bulk.shared::cta.global.mbarrier::complete_tx::bytes "
        "[%0], [%1], %2, [%3];"
        :: "r"(dst), "l"(src), "r"(bytes), "r"(mbar) : "memory");
}
__device__ __forceinline__ uint64_t make_desc_sw128(uint32_t base) {
    const uint64_t DESC_BASE =
        (uint64_t(2)  << 61) | (uint64_t(1) << 46) |
        (uint64_t(64) << 32) | (uint64_t(1) << 16);
    return DESC_BASE | ((uint64_t)(base >> 4) & 0x3FFF);
}
__device__ __forceinline__ uint32_t elect_one() {
    uint32_t pred;
    asm volatile(
        "{\n\t.reg .pred p;\n\t"
        "elect.sync _|p, 0xFFFFFFFF;\n\t"
        "selp.b32 %0, 1, 0, p;\n\t}"
        : "=r"(pred));
    return pred;
}
// kind::f16 idesc: F32@4, BF16@7, BF16@10, N-field [16:23)=N/4, M-field=(M>>4)<<24
#define MMA_IDESC ((1u << 4) | (1u << 7) | (1u << 10) | ((BN / 4) << 16) | ((SM_TILE >> 4) << 24))

__device__ __forceinline__ void mma_f16_ss(uint32_t d_tmem, uint64_t a_desc,
                                           uint64_t b_desc, uint32_t en) {
    asm volatile(
        "{\n\t.reg .pred p;\n\t"
        "setp.ne.u32 p, %5, 0;\n\t"
        "tcgen05.mma.cta_group::1.kind::f16 [%0], %1, %2, %3, {%4, %4, %4, %4}, p;\n\t}"
        :: "r"(d_tmem), "l"(a_desc), "l"(b_desc), "r"(MMA_IDESC), "r"(0u), "r"(en)
        : "memory");
}
#define BAR_EPI() asm volatile("bar.sync 1, 128;" ::: "memory")
#endif  // HAS_TC

#if HAS_TC
__global__ void __launch_bounds__(160) __cluster_dims__(1, 1, 1)
#else
__global__ void __launch_bounds__(160)
#endif
gemm_tc(const float* __restrict__ wscale,
        const float* __restrict__ bias,
        float* __restrict__ out) {
#if HAS_TC
    extern __shared__ char smem[];
    const uint32_t sb = smem_u32(smem);
    const int tid = threadIdx.x, wid = tid >> 5, lane = tid & 31;

    // warp 0 allocs 512 TMEM cols once; no relinquish (R9 fix)
    if (wid == 0) {
        asm volatile("tcgen05.alloc.cta_group::1.sync.aligned.shared::cta.b32 [%0], %1;"
                     :: "r"(sb + OFF_TMEM), "r"(512u) : "memory");
    }
    if (tid == 0) {
#pragma unroll
        for (int s = 0; s < STAGES; ++s) {
            mbar_init(sb + OFF_FULL + 8 * s, 1);
            mbar_init(sb + OFF_DONE + 8 * s, 1);
        }
    }
    __syncthreads();

    uint32_t tmem;
    asm volatile("ld.shared.b32 %0, [%1];" : "=r"(tmem) : "r"(sb + OFF_TMEM));

    const float* wsS = (const float*)(smem + OFF_WS);
    const float* bS  = (const float*)(smem + OFF_BIAS);

    if (wid == 4) {
        // ===================== LOADER (warp 4) =====================
        int g = 0;
        for (int t = blockIdx.x; t < NTILES; t += GRID) {
            const int bn = t & 15, bm = t >> 4;
            const char* Asrc = reinterpret_cast<const char*>(g_qx_t)
                             + (size_t)bm * 64 * TILE_KS_BYTES;
            const char* Bsrc = reinterpret_cast<const char*>(g_wb_t)
                             + (size_t)bn * 64 * TILE_KS_BYTES;
            for (int s = 0; s < NIT; ++s, ++g) {
                const int b = g % STAGES;
                if (g >= STAGES)
                    mbar_wait(sb + OFF_DONE + 8 * b, ((g / STAGES) - 1) & 1);
                if (elect_one()) {
                    const uint32_t dst = sb + OFF_STAGE + b * STAGE_BYTES;
                    const uint32_t fb  = sb + OFF_FULL + 8 * b;
                    mbar_expect_tx(fb, STAGE_BYTES);
                    bulk_g2s(dst, Asrc + (size_t)s * TILE_KS_BYTES,
                             TILE_KS_BYTES, fb);
                    bulk_g2s(dst + TILE_KS_BYTES, Bsrc + (size_t)s * TILE_KS_BYTES,
                             TILE_KS_BYTES, fb);
                }
            }
        }
    } else {
        // ============= MMA (warp 0) + epilogue (warps 0-3) =============
        int g = 0;
        for (int t = blockIdx.x; t < NTILES; t += GRID) {
            const int bn = t & 15, bm = t >> 4;

            if (wid == 0) {
                // mainloop: whole warp runs; elect guards MMA/commit
                for (int it = 0; it < NIT; ++it, ++g) {
                    const int b = g % STAGES;
                    mbar_wait(sb + OFF_FULL + 8 * b, (g / STAGES) & 1);
                    if (elect_one()) {
                        const uint32_t base = sb + OFF_STAGE + b * STAGE_BYTES;
                        const uint64_t a0d = make_desc_sw128(base);
                        const uint64_t a1d = make_desc_sw128(base + A_SUB_BYTES);
                        const uint64_t bd  = make_desc_sw128(base + TILE_KS_BYTES);
                        const uint32_t en0 = (it > 0) ? 1u : 0u;
#pragma unroll
                        for (int k = 0; k < KSTEPS; ++k) {
                            const uint32_t en = (k > 0) ? 1u : en0;
                            mma_f16_ss(tmem,       a0d + k * 2, bd + k * 2, en);
                            mma_f16_ss(tmem + 256, a1d + k * 2, bd + k * 2, en);
                        }
                        tc_commit(sb + OFF_DONE + 8 * b);
                    }
                }
                // all MMAs of this tile complete (commits in order)
                mbar_wait(sb + OFF_DONE + 8 * ((g - 1) % STAGES),
                          ((g - 1) / STAGES) & 1);
            } else {
                // warps 1-3: preload ws/bias for this tile (after prev epi bar)
                g += NIT;
                const int n0 = bn * BN;
                for (int i = tid - 32; i < BN; i += 96) {
                    ((float*)(smem + OFF_WS))[i]   = wscale[n0 + i];
                    ((float*)(smem + OFF_BIAS))[i] = bias[n0 + i];
                }
            }

            BAR_EPI();   // MMA done AND ws/bias(t) loaded
            asm volatile("tcgen05.fence::after_thread_sync;" ::: "memory");

            // ---- epilogue: warps 0-3 ----
#pragma unroll
            for (int sub = 0; sub < 2; ++sub) {
                const int m = bm * BM + sub * SM_TILE + wid * 32 + lane;
                const float xs = g_xscale[m];
                float* orow = out + (size_t)m * N_DIM + bn * BN;
                const uint32_t dbase = tmem + sub * 256;

#pragma unroll
                for (int ch = 0; ch < BN / 32; ++ch) {
                    uint32_t r[32];
                    asm volatile(
                        "tcgen05.ld.sync.aligned.32x32b.x32.b32 "
                        "{%0, %1, %2, %3, %4, %5, %6, %7, "
                        " %8, %9, %10, %11, %12, %13, %14, %15, "
                        " %16, %17, %18, %19, %20, %21, %22, %23, "
                        " %24, %25, %26, %27, %28, %29, %30, %31}, [%32];"
                        : "=r"(r[0]),  "=r"(r[1]),  "=r"(r[2]),  "=r"(r[3]),
                          "=r"(r[4]),  "=r"(r[5]),  "=r"(r[6]),  "=r"(r[7]),
                          "=r"(r[8]),  "=r"(r[9]),  "=r"(r[10]), "=r"(r[11]),
                          "=r"(r[12]), "=r"(r[13]), "=r"(r[14]), "=r"(r[15]),
                          "=r"(r[16]), "=r"(r[17]), "=r"(r[18]), "=r"(r[19]),
                          "=r"(r[20]), "=r"(r[21]), "=r"(r[22]), "=r"(r[23]),
                          "=r"(r[24]), "=r"(r[25]), "=r"(r[26]), "=r"(r[27]),
                          "=r"(r[28]), "=r"(r[29]), "=r"(r[30]), "=r"(r[31])
                        : "r"(dbase + ch * 32));
                    asm volatile("tcgen05.wait::ld.sync.aligned;" ::: "memory");

#pragma unroll
                    for (int q = 0; q < 8; ++q) {
                        const int c = ch * 32 + q * 4;
                        float4 v;
                        v.x = __uint_as_float(r[q * 4 + 0]) * wsS[c + 0] * xs + bS[c + 0];
                        v.y = __uint_as_float(r[q * 4 + 1]) * wsS[c + 1] * xs + bS[c + 1];
                        v.z = __uint_as_float(r[q * 4 + 2]) * wsS[c + 2] * xs + bS[c + 2];
                        v.w = __uint_as_float(r[q * 4 + 3]) * wsS[c + 3] * xs + bS[c + 3];
                        *reinterpret_cast<float4*>(orow + c) = v;
                    }
                }
            }
            asm volatile("tcgen05.fence::before_thread_sync;" ::: "memory");
            BAR_EPI();   // epilogue reads done -> next tile may overwrite D
        }
    }

    __syncthreads();
    if (tid == 0) {
#pragma unroll
        for (int s = 0; s < STAGES; ++s) {
            asm volatile("mbarrier.inval.shared.b64 [%0];"
                         :: "r"(sb + OFF_FULL + 8 * s) : "memory");
            asm volatile("mbarrier.inval.shared.b64 [%0];"
                         :: "r"(sb + OFF_DONE + 8 * s) : "memory");
        }
    }
    __syncthreads();
    if (wid == 0) {
        asm volatile("tcgen05.dealloc.cta_group::1.sync.aligned.b32 %0, %1;"
                     :: "r"(tmem), "r"(512u));
    }
#endif  // HAS_TC
}

// ---------------------------------------------------------------------------
extern "C" void kernel_launch(void* const* d_in, const int* in_sizes, int n_in,
                              void* d_out, int out_size) {
    const float* x      = (const float*)d_in[0];
    const void*  weight = d_in[1];
    const float* wscale = (const float*)d_in[2];
    const float* bias   = (const float*)d_in[3];
    float* out = (float*)d_out;

    const int T = in_sizes[0] / K_DIM;   // 8192

    cudaFuncSetAttribute(gemm_tc, cudaFuncAttributeMaxDynamicSharedMemorySize,
                         SMEM_TOTAL);

    detect_kernel<<<1, 32>>>((const int*)weight);
    pack_kernel<<<(N_DIM * K_DIM / 4) / 256, 256>>>(weight);
    quant_kernel<<<T, 256>>>(x);

    gemm_tc<<<GRID, 160, SMEM_TOTAL>>>(wscale, bias, out);
}